// round 5
// baseline (speedup 1.0000x reference)
#include <cuda_runtime.h>
#include <cuda_bf16.h>
#include <math.h>

// ---------------------------------------------------------------------------
// EncoderGRUODE: B=256, T=512, D_IN=64, H=128
// Sequential scan over T; rows independent -> persistent CTA per 2 rows.
// ---------------------------------------------------------------------------

#define B_   256
#define T_   512
#define DIN  64
#define H_   128
#define G3   (3 * H_)   // 384

// Packed W_hh in k-major layout for coalesced streaming from L2:
//   g_whh_rz[k*128 + t] = (W_hh[t][k], W_hh[128+t][k])
//   g_whh_n [k*128 + t] =  W_hh[256+t][k]
__device__ float2 g_whh_rz[H_ * H_];
__device__ float  g_whh_n [H_ * H_];
__device__ int    g_mask[T_];
__device__ float  g_dt[T_];

// ---------------------------------------------------------------------------
// Prep: pack W_hh, decode mask (uint8 / int32 / float32 robust), compute dts
// ---------------------------------------------------------------------------
__global__ void prep_kernel(const float* __restrict__ W_hh,
                            const unsigned char* __restrict__ mask_raw,
                            const float* __restrict__ tp)
{
    int gtid = blockIdx.x * blockDim.x + threadIdx.x;
    int nthr = gridDim.x * blockDim.x;

    for (int idx = gtid; idx < H_ * H_; idx += nthr) {
        int k = idx >> 7;
        int t = idx & 127;
        float2 rz;
        rz.x = W_hh[t * H_ + k];
        rz.y = W_hh[(H_ + t) * H_ + k];
        g_whh_rz[idx] = rz;
        g_whh_n[idx]  = W_hh[(2 * H_ + t) * H_ + k];
    }

    // dts: ts = [tp0[0]-0.01, tp0...]; dt[0]=0.01, dt[t]=tp0[t]-tp0[t-1]
    if (gtid < T_) {
        g_dt[gtid] = (gtid == 0) ? 0.01f : (tp[gtid] - tp[gtid - 1]);
    }

    // mask dtype detection (single thread; trivial cost)
    if (blockIdx.x == 0 && threadIdx.x == 0) {
        bool nz_nonmult = false, one_mult = false;
        bool f32_sig = true;
        for (int i = 0; i < T_; i++) {
            unsigned char v = mask_raw[i];
            int m4 = i & 3;
            if (m4 != 0 && v) nz_nonmult = true;
            if (m4 == 0 && v == 1) one_mult = true;
            // float32 1.0f bytes: [00,00,80,3F]; 0.0f: all zero
            if (m4 == 0 || m4 == 1) { if (v != 0) f32_sig = false; }
            else if (m4 == 2)       { if (v != 0 && v != 0x80) f32_sig = false; }
            else                    { if (v != 0 && v != 0x3F) f32_sig = false; }
        }
        if (!nz_nonmult && one_mult) {
            const int* mi = (const int*)mask_raw;
            for (int i = 0; i < T_; i++) g_mask[i] = (mi[i] != 0);
        } else if (nz_nonmult && f32_sig) {
            const float* mf = (const float*)mask_raw;
            for (int i = 0; i < T_; i++) g_mask[i] = (mf[i] != 0.0f);
        } else {
            for (int i = 0; i < T_; i++) g_mask[i] = (mask_raw[i] != 0);
        }
    }
}

// ---------------------------------------------------------------------------
// Main persistent kernel: 128 CTAs x 128 threads, 2 rows per CTA.
// SMEM: W_node (pad 132), W_ih (pad 68), W_out (pad 132), biases, state bufs.
// ---------------------------------------------------------------------------

#define WN_STRIDE  132
#define WIH_STRIDE 68
#define WO_STRIDE  132

#define SM_WNODE  0
#define SM_WIH    (SM_WNODE + H_ * WN_STRIDE)         // 16896
#define SM_WOUT   (SM_WIH + G3 * WIH_STRIDE)          // +26112
#define SM_BN     (SM_WOUT + DIN * WO_STRIDE)         // +8448
#define SM_BIH    (SM_BN + H_)
#define SM_BHH    (SM_BIH + G3)
#define SM_BOUT   (SM_BHH + G3)
#define SM_H0     (SM_BOUT + DIN)
#define SM_H1     (SM_H0 + H_)
#define SM_AA0    (SM_H1 + H_)
#define SM_AA1    (SM_AA0 + H_)
#define SM_AB0    (SM_AA1 + H_)
#define SM_AB1    (SM_AB0 + H_)
#define SM_HO0    (SM_AB1 + H_)
#define SM_HO1    (SM_HO0 + H_)
#define SM_IN0    (SM_HO1 + H_)
#define SM_IN1    (SM_IN0 + DIN)
#define SM_PO0    (SM_IN1 + DIN)
#define SM_PO1    (SM_PO0 + DIN)
#define SM_TOTAL  (SM_PO1 + DIN)                       // floats
#define SMEM_BYTES (SM_TOTAL * 4)

__device__ __forceinline__ float sigmoidf_(float x) {
    return 1.0f / (1.0f + expf(-x));
}

__global__ void __launch_bounds__(128, 1)
enc_gruode_kernel(const float* __restrict__ x,
                  const float* __restrict__ W_ih,
                  const float* __restrict__ b_ih,
                  const float* __restrict__ b_hh,
                  const float* __restrict__ W_node,
                  const float* __restrict__ b_node,
                  const float* __restrict__ W_out,
                  const float* __restrict__ b_out,
                  float* __restrict__ out)
{
    extern __shared__ float sm[];
    const int tid = threadIdx.x;

    // ---- stage weights into SMEM ----
    for (int i = tid; i < H_ * H_; i += 128)
        sm[SM_WNODE + (i >> 7) * WN_STRIDE + (i & 127)] = W_node[i];
    for (int i = tid; i < G3 * DIN; i += 128)
        sm[SM_WIH + (i >> 6) * WIH_STRIDE + (i & 63)] = W_ih[i];
    for (int i = tid; i < DIN * H_; i += 128)
        sm[SM_WOUT + (i >> 7) * WO_STRIDE + (i & 127)] = W_out[i];
    sm[SM_BN + tid] = b_node[tid];
    for (int i = tid; i < G3; i += 128) {
        sm[SM_BIH + i] = b_ih[i];
        sm[SM_BHH + i] = b_hh[i];
    }
    if (tid < DIN) {
        float bo = b_out[tid];
        sm[SM_BOUT + tid] = bo;
        sm[SM_PO0 + tid] = bo;   // prev_out at t=0 with h0=0 is b_out
        sm[SM_PO1 + tid] = bo;
    }
    sm[SM_H0 + tid] = 0.0f;
    sm[SM_H1 + tid] = 0.0f;
    __syncthreads();

    const int row0 = blockIdx.x * 2;
    const int row1 = row0 + 1;
    const float* __restrict__ x0 = x + (size_t)row0 * T_ * DIN;
    const float* __restrict__ x1 = x + (size_t)row1 * T_ * DIN;
    float* __restrict__ o0 = out + (size_t)row0 * T_ * DIN;
    float* __restrict__ o1 = out + (size_t)row1 * T_ * DIN;

    const float* wn_row = sm + SM_WNODE + tid * WN_STRIDE;
    const float  bnv    = sm[SM_BN + tid];

    const float* h0s  = sm + SM_H0;
    const float* h1s  = sm + SM_H1;
    float* aa0 = sm + SM_AA0;  float* aa1 = sm + SM_AA1;
    float* ab0 = sm + SM_AB0;  float* ab1 = sm + SM_AB1;
    float* ho0 = sm + SM_HO0;  float* ho1 = sm + SM_HO1;
    float* in0 = sm + SM_IN0;  float* in1 = sm + SM_IN1;
    float* po0 = sm + SM_PO0;  float* po1 = sm + SM_PO1;

    // GRU weight rows (SMEM, padded stride)
    const float* wih_r = sm + SM_WIH + tid * WIH_STRIDE;
    const float* wih_z = sm + SM_WIH + (H_ + tid) * WIH_STRIDE;
    const float* wih_n = sm + SM_WIH + (2 * H_ + tid) * WIH_STRIDE;
    const float bih_r = sm[SM_BIH + tid];
    const float bih_z = sm[SM_BIH + H_ + tid];
    const float bih_n = sm[SM_BIH + 2 * H_ + tid];
    const float bhh_r = sm[SM_BHH + tid];
    const float bhh_z = sm[SM_BHH + H_ + tid];
    const float bhh_n = sm[SM_BHH + 2 * H_ + tid];

    float hreg0 = 0.0f, hreg1 = 0.0f;

    // one RK4 mat-vec + tanh for both rows
    auto rksub = [&](const float* s0, const float* s1, float& kk0, float& kk1) {
        float a0 = 0.f, b0 = 0.f, a1 = 0.f, b1 = 0.f;
#pragma unroll
        for (int k = 0; k < H_; k += 8) {
            float4 w0 = *(const float4*)(wn_row + k);
            float4 w1 = *(const float4*)(wn_row + k + 4);
            float4 u0 = *(const float4*)(s0 + k);
            float4 u1 = *(const float4*)(s0 + k + 4);
            float4 v0 = *(const float4*)(s1 + k);
            float4 v1 = *(const float4*)(s1 + k + 4);
            a0 = fmaf(w0.x, u0.x, a0); a1 = fmaf(w0.x, v0.x, a1);
            a0 = fmaf(w0.y, u0.y, a0); a1 = fmaf(w0.y, v0.y, a1);
            a0 = fmaf(w0.z, u0.z, a0); a1 = fmaf(w0.z, v0.z, a1);
            a0 = fmaf(w0.w, u0.w, a0); a1 = fmaf(w0.w, v0.w, a1);
            b0 = fmaf(w1.x, u1.x, b0); b1 = fmaf(w1.x, v1.x, b1);
            b0 = fmaf(w1.y, u1.y, b0); b1 = fmaf(w1.y, v1.y, b1);
            b0 = fmaf(w1.z, u1.z, b0); b1 = fmaf(w1.z, v1.z, b1);
            b0 = fmaf(w1.w, u1.w, b0); b1 = fmaf(w1.w, v1.w, b1);
        }
        kk0 = tanhf(a0 + b0 + bnv);
        kk1 = tanhf(a1 + b1 + bnv);
    };

    for (int t = 0; t < T_; ++t) {
        const float dt  = g_dt[t];
        const float hdt = 0.5f * dt;
        const int   msk = g_mask[t];

        // -------- RK4 --------
        float k0, k1, ks0, ks1;
        rksub(h0s, h1s, k0, k1);                    // k1
        ks0 = k0; ks1 = k1;
        aa0[tid] = hreg0 + hdt * k0;
        aa1[tid] = hreg1 + hdt * k1;
        __syncthreads();

        rksub(aa0, aa1, k0, k1);                    // k2
        ks0 += 2.0f * k0; ks1 += 2.0f * k1;
        ab0[tid] = hreg0 + hdt * k0;
        ab1[tid] = hreg1 + hdt * k1;
        __syncthreads();

        rksub(ab0, ab1, k0, k1);                    // k3
        ks0 += 2.0f * k0; ks1 += 2.0f * k1;
        aa0[tid] = hreg0 + dt * k0;
        aa1[tid] = hreg1 + dt * k1;
        __syncthreads();

        rksub(aa0, aa1, k0, k1);                    // k4
        const float c = dt * (1.0f / 6.0f);
        float hode0 = hreg0 + c * (ks0 + k0);
        float hode1 = hreg1 + c * (ks1 + k1);
        ho0[tid] = hode0;
        ho1[tid] = hode1;

        // -------- input vector (teacher forcing) --------
        if (tid < DIN) {
            in0[tid] = msk ? x0[(size_t)t * DIN + tid] : po0[tid];
        } else {
            int j = tid - DIN;
            in1[j] = msk ? x1[(size_t)t * DIN + j] : po1[j];
        }
        __syncthreads();

        // -------- GRU cell --------
        float ir0 = bih_r, iz0 = bih_z, inn0 = bih_n;
        float ir1 = bih_r, iz1 = bih_z, inn1 = bih_n;
#pragma unroll
        for (int k = 0; k < DIN; k += 4) {
            float4 wr = *(const float4*)(wih_r + k);
            float4 wz = *(const float4*)(wih_z + k);
            float4 wn = *(const float4*)(wih_n + k);
            float4 u  = *(const float4*)(in0 + k);
            float4 v  = *(const float4*)(in1 + k);
            ir0 = fmaf(wr.x, u.x, ir0); ir1 = fmaf(wr.x, v.x, ir1);
            ir0 = fmaf(wr.y, u.y, ir0); ir1 = fmaf(wr.y, v.y, ir1);
            ir0 = fmaf(wr.z, u.z, ir0); ir1 = fmaf(wr.z, v.z, ir1);
            ir0 = fmaf(wr.w, u.w, ir0); ir1 = fmaf(wr.w, v.w, ir1);
            iz0 = fmaf(wz.x, u.x, iz0); iz1 = fmaf(wz.x, v.x, iz1);
            iz0 = fmaf(wz.y, u.y, iz0); iz1 = fmaf(wz.y, v.y, iz1);
            iz0 = fmaf(wz.z, u.z, iz0); iz1 = fmaf(wz.z, v.z, iz1);
            iz0 = fmaf(wz.w, u.w, iz0); iz1 = fmaf(wz.w, v.w, iz1);
            inn0 = fmaf(wn.x, u.x, inn0); inn1 = fmaf(wn.x, v.x, inn1);
            inn0 = fmaf(wn.y, u.y, inn0); inn1 = fmaf(wn.y, v.y, inn1);
            inn0 = fmaf(wn.z, u.z, inn0); inn1 = fmaf(wn.z, v.z, inn1);
            inn0 = fmaf(wn.w, u.w, inn0); inn1 = fmaf(wn.w, v.w, inn1);
        }

        float hr0 = bhh_r, hz0 = bhh_z, hn0 = bhh_n;
        float hr1 = bhh_r, hz1 = bhh_z, hn1 = bhh_n;
#pragma unroll 16
        for (int k = 0; k < H_; ++k) {
            const float2 w  = g_whh_rz[k * H_ + tid];   // coalesced LDG.64
            const float  wn = g_whh_n [k * H_ + tid];   // coalesced LDG.32
            const float  u  = ho0[k];
            const float  v  = ho1[k];
            hr0 = fmaf(w.x, u, hr0);  hr1 = fmaf(w.x, v, hr1);
            hz0 = fmaf(w.y, u, hz0);  hz1 = fmaf(w.y, v, hz1);
            hn0 = fmaf(wn,  u, hn0);  hn1 = fmaf(wn,  v, hn1);
        }

        {
            float r0 = sigmoidf_(ir0 + hr0);
            float z0 = sigmoidf_(iz0 + hz0);
            float n0 = tanhf(inn0 + r0 * hn0);
            hreg0 = (1.0f - z0) * n0 + z0 * hode0;
            sm[SM_H0 + tid] = hreg0;

            float r1 = sigmoidf_(ir1 + hr1);
            float z1 = sigmoidf_(iz1 + hz1);
            float n1 = tanhf(inn1 + r1 * hn1);
            hreg1 = (1.0f - z1) * n1 + z1 * hode1;
            sm[SM_H1 + tid] = hreg1;
        }
        __syncthreads();

        // -------- output projection (also the next step's prev_out) --------
        {
            const float* hs;
            float* os;
            float* pos;
            int j;
            if (tid < DIN) { j = tid;        hs = h0s; os = o0; pos = po0; }
            else           { j = tid - DIN;  hs = h1s; os = o1; pos = po1; }
            float acc = sm[SM_BOUT + j];
            const float* wo = sm + SM_WOUT + j * WO_STRIDE;
#pragma unroll
            for (int k = 0; k < H_; k += 4) {
                float4 w = *(const float4*)(wo + k);
                float4 u = *(const float4*)(hs + k);
                acc = fmaf(w.x, u.x, acc);
                acc = fmaf(w.y, u.y, acc);
                acc = fmaf(w.z, u.z, acc);
                acc = fmaf(w.w, u.w, acc);
            }
            os[(size_t)t * DIN + j] = acc;
            pos[j] = acc;
        }
        __syncthreads();
    }
}

// ---------------------------------------------------------------------------
extern "C" void kernel_launch(void* const* d_in, const int* in_sizes, int n_in,
                              void* d_out, int out_size)
{
    const float*         x      = (const float*)d_in[0];
    const float*         tp     = (const float*)d_in[1];
    const unsigned char* mask   = (const unsigned char*)d_in[2];
    const float*         W_ih   = (const float*)d_in[3];
    const float*         W_hh   = (const float*)d_in[4];
    const float*         b_ih   = (const float*)d_in[5];
    const float*         b_hh   = (const float*)d_in[6];
    const float*         W_node = (const float*)d_in[7];
    const float*         b_node = (const float*)d_in[8];
    const float*         W_out  = (const float*)d_in[9];
    const float*         b_out  = (const float*)d_in[10];
    float*               out    = (float*)d_out;

    prep_kernel<<<64, 256>>>(W_hh, mask, tp);

    cudaFuncSetAttribute(enc_gruode_kernel,
                         cudaFuncAttributeMaxDynamicSharedMemorySize,
                         SMEM_BYTES);
    enc_gruode_kernel<<<B_ / 2, 128, SMEM_BYTES>>>(
        x, W_ih, b_ih, b_hh, W_node, b_node, W_out, b_out, out);
}

// round 6
// speedup vs baseline: 1.8340x; 1.8340x over previous
#include <cuda_runtime.h>
#include <math.h>

// ---------------------------------------------------------------------------
// EncoderGRUODE: B=256, T=512, D_IN=64, H=128
// 128 CTAs x 256 threads. Thread (half = tid>>7, i = tid&127) owns element i
// of row `half` and the k-half [64*half, 64*half+64) of all weight dots.
// W_node + W_ih in registers; W_hh packed k-major in SMEM; W_out from L2.
// ---------------------------------------------------------------------------

#define B_   256
#define T_   512
#define DIN  64
#define H_   128

// packed weights produced by prep_kernel
__device__ float4 g_whh4[12288];   // [0:4096) R, [4096:8192) Z, [8192:12288) N ; idx=(k/4)*128+i
__device__ float4 g_wout4[2048];   // idx = (k/4)*64 + j  -> {W_out[j][k..k+3]}
__device__ int    g_mask[T_];
__device__ float  g_dt[T_];

// ---------------------------------------------------------------------------
__global__ void prep_kernel(const float* __restrict__ W_hh,
                            const float* __restrict__ W_out,
                            const unsigned char* __restrict__ mask_raw,
                            const float* __restrict__ tp)
{
    int gtid = blockIdx.x * blockDim.x + threadIdx.x;
    int nthr = gridDim.x * blockDim.x;

    for (int idx = gtid; idx < 4096; idx += nthr) {
        int kq = idx >> 7, i = idx & 127, k = kq * 4;
        g_whh4[idx] = make_float4(W_hh[i * H_ + k],     W_hh[i * H_ + k + 1],
                                  W_hh[i * H_ + k + 2], W_hh[i * H_ + k + 3]);
        int iz = H_ + i;
        g_whh4[4096 + idx] = make_float4(W_hh[iz * H_ + k],     W_hh[iz * H_ + k + 1],
                                         W_hh[iz * H_ + k + 2], W_hh[iz * H_ + k + 3]);
        int in_ = 2 * H_ + i;
        g_whh4[8192 + idx] = make_float4(W_hh[in_ * H_ + k],     W_hh[in_ * H_ + k + 1],
                                         W_hh[in_ * H_ + k + 2], W_hh[in_ * H_ + k + 3]);
    }
    for (int idx = gtid; idx < 2048; idx += nthr) {
        int kq = idx >> 6, j = idx & 63, k = kq * 4;
        g_wout4[idx] = make_float4(W_out[j * H_ + k],     W_out[j * H_ + k + 1],
                                   W_out[j * H_ + k + 2], W_out[j * H_ + k + 3]);
    }
    if (gtid < T_)
        g_dt[gtid] = (gtid == 0) ? 0.01f : (tp[gtid] - tp[gtid - 1]);

    // robust mask decode (uint8 / int32 / float32) — unchanged from R5 (passed)
    if (blockIdx.x == 0 && threadIdx.x == 0) {
        bool nz_nonmult = false, one_mult = false, f32_sig = true;
        for (int i = 0; i < T_; i++) {
            unsigned char v = mask_raw[i];
            int m4 = i & 3;
            if (m4 != 0 && v) nz_nonmult = true;
            if (m4 == 0 && v == 1) one_mult = true;
            if (m4 == 0 || m4 == 1) { if (v != 0) f32_sig = false; }
            else if (m4 == 2)       { if (v != 0 && v != 0x80) f32_sig = false; }
            else                    { if (v != 0 && v != 0x3F) f32_sig = false; }
        }
        if (!nz_nonmult && one_mult) {
            const int* mi = (const int*)mask_raw;
            for (int i = 0; i < T_; i++) g_mask[i] = (mi[i] != 0);
        } else if (nz_nonmult && f32_sig) {
            const float* mf = (const float*)mask_raw;
            for (int i = 0; i < T_; i++) g_mask[i] = (mf[i] != 0.0f);
        } else {
            for (int i = 0; i < T_; i++) g_mask[i] = (mask_raw[i] != 0);
        }
    }
}

// ---------------------------------------------------------------------------
// SMEM layout (float offsets)
#define SMF_WHH   0        // 49152 floats = 12288 float4 (R | Z | N)
#define SMF_S     49152    // 256: s0[0:128) s1[128:256)  (current/stage state)
#define SMF_HO    49408    // 256: h_ode rows 0/1
#define SMF_XK    49664    // 256: RK4 stage partial exchange [row*128+i]
#define SMF_IG    49920    // 1536: i-gate partials [( (g*2+row)*2 + half )*128 + i]
#define SMF_WH    51456    // 768:  W_hh foreign partials [(g*2+row)*128 + i]
#define SMF_INP   52224    // 128: inp [row*64+j]
#define SMF_PO    52352    // 128: prev_out [row*64+j]
#define SMF_XO    52480    // 128: out-proj khalf exchange
#define SMF_BN    52608    // 128
#define SMF_BIH   52736    // 384
#define SMF_BHH   53120    // 384
#define SMF_BOUT  53504    // 64
#define SMF_DT    53568    // 512
#define SMF_MSK   54080    // 512 ints
#define SMF_TOTAL 54592
#define SMEM_BYTES (SMF_TOTAL * 4)

__device__ __forceinline__ float tanh_fast(float x) {
    float y;
    asm("tanh.approx.f32 %0, %1;" : "=f"(y) : "f"(x));
    return y;
}
__device__ __forceinline__ float sigmoidf_(float x) {
    return 1.0f / (1.0f + expf(-x));
}

#define DOT4_2(A0, A1, W, U) \
    A0 = fmaf((W).x, (U).x, A0); A0 = fmaf((W).y, (U).y, A0); \
    A1 = fmaf((W).z, (U).z, A1); A1 = fmaf((W).w, (U).w, A1);
#define DOT4_1(A, W, U) \
    A = fmaf((W).x, (U).x, A); A = fmaf((W).y, (U).y, A); \
    A = fmaf((W).z, (U).z, A); A = fmaf((W).w, (U).w, A);

__global__ void __launch_bounds__(256, 1)
enc_gruode_kernel(const float* __restrict__ x,
                  const float* __restrict__ W_ih,
                  const float* __restrict__ b_ih,
                  const float* __restrict__ b_hh,
                  const float* __restrict__ W_node,
                  const float* __restrict__ b_node,
                  const float* __restrict__ b_out,
                  float* __restrict__ out)
{
    extern __shared__ float sm[];
    int* smi = (int*)sm;
    const int tid  = threadIdx.x;
    const int i    = tid & 127;
    const int half = tid >> 7;

    // ---- stage packed W_hh into SMEM (coalesced LDG.128 -> conflict-free STS) ----
    {
        float4* s4 = (float4*)sm;
        for (int idx = tid; idx < 12288; idx += 256) s4[idx] = g_whh4[idx];
    }
    for (int idx = tid; idx < 512; idx += 256) {
        sm[SMF_DT + idx]   = g_dt[idx];
        smi[SMF_MSK + idx] = g_mask[idx];
    }
    if (tid < 128) sm[SMF_BN + tid] = b_node[tid];
    for (int idx = tid; idx < 384; idx += 256) {
        sm[SMF_BIH + idx] = b_ih[idx];
        sm[SMF_BHH + idx] = b_hh[idx];
    }
    if (tid < 64) sm[SMF_BOUT + tid] = b_out[tid];
    if (tid < 128) sm[SMF_PO + tid] = b_out[tid & 63];  // prev_out at t=0 (h0=0)
    sm[SMF_S + tid] = 0.0f;                             // both rows' state = 0

    // ---- per-thread register weights ----
    float4 wn4[16];                       // W_node[i][64*half .. +64)
    {
        const float4* src = (const float4*)(W_node + (size_t)i * H_ + half * 64);
#pragma unroll
        for (int q = 0; q < 16; q++) wn4[q] = src[q];
    }
    float4 wihr[8], wihz[8], wihn[8];     // W_ih rows (r,z,n)[i][32*half .. +32)
    {
        const float4* sr = (const float4*)(W_ih + (size_t)i * DIN + half * 32);
        const float4* sz = (const float4*)(W_ih + (size_t)(H_ + i) * DIN + half * 32);
        const float4* sn = (const float4*)(W_ih + (size_t)(2 * H_ + i) * DIN + half * 32);
#pragma unroll
        for (int p = 0; p < 8; p++) { wihr[p] = sr[p]; wihz[p] = sz[p]; wihn[p] = sn[p]; }
    }
    __syncthreads();

    const float bn_i = sm[SMF_BN + i];
    const float* xr = x + (size_t)(2 * blockIdx.x + ((tid >> 6) & 1)) * T_ * DIN;
    float* orow = out + (size_t)(2 * blockIdx.x + half) * T_ * DIN;

    const float4* u4 = (const float4*)(sm + SMF_S) + 16 * half;         // row0 state, my k-half
    const float4* v4 = (const float4*)(sm + SMF_S + 128) + 16 * half;   // row1 state
    const float4* hu = (const float4*)(sm + SMF_HO) + 16 * half;
    const float4* hv = (const float4*)(sm + SMF_HO + 128) + 16 * half;
    const float4* WR = ((const float4*)sm) + 16 * half * 128;
    const float4* WZ = ((const float4*)sm) + 4096 + 16 * half * 128;
    const float4* WN = ((const float4*)sm) + 8192 + 16 * half * 128;
    const float4* iu = (const float4*)(sm + SMF_INP) + 8 * half;
    const float4* iv = (const float4*)(sm + SMF_INP + 64) + 8 * half;

    float hreg = 0.0f;

    auto stage_partial = [&](float& P0, float& P1) {
        float a0 = 0.f, a1 = 0.f, c0 = 0.f, c1 = 0.f;
#pragma unroll
        for (int q = 0; q < 16; q++) {
            float4 w = wn4[q];
            float4 a = u4[q];
            float4 b = v4[q];
            DOT4_2(a0, a1, w, a);
            DOT4_2(c0, c1, w, b);
        }
        P0 = a0 + a1; P1 = c0 + c1;
    };

    for (int t = 0; t < T_; ++t) {
        const float dt  = sm[SMF_DT + t];
        const int   msk = smi[SMF_MSK + t];
        const float hdt = 0.5f * dt;

        // input staging value (threads 0..127): x[t] or prev_out
        float xv = 0.0f;
        if (tid < 128)
            xv = msk ? xr[(size_t)t * DIN + (tid & 63)] : sm[SMF_PO + tid];

        float p0, p1, kv, ksum;

        // ---------------- RK4 stage 1 ----------------
        stage_partial(p0, p1);
        if (half == 0) sm[SMF_XK + 128 + i] = p1; else sm[SMF_XK + i] = p0;
        if (tid < 128) sm[SMF_INP + tid] = xv;
        __syncthreads();                                               // B1
        kv = tanh_fast((half ? p1 : p0) + sm[SMF_XK + half * 128 + i] + bn_i);
        ksum = kv;
        sm[SMF_S + half * 128 + i] = fmaf(hdt, kv, hreg);
        __syncthreads();                                               // B2

        // ---------------- RK4 stage 2 ----------------
        stage_partial(p0, p1);
        if (half == 0) sm[SMF_XK + 128 + i] = p1; else sm[SMF_XK + i] = p0;
        __syncthreads();                                               // B3
        kv = tanh_fast((half ? p1 : p0) + sm[SMF_XK + half * 128 + i] + bn_i);
        ksum = fmaf(2.0f, kv, ksum);
        sm[SMF_S + half * 128 + i] = fmaf(hdt, kv, hreg);
        __syncthreads();                                               // B4

        // ---------------- RK4 stage 3 ----------------
        stage_partial(p0, p1);
        if (half == 0) sm[SMF_XK + 128 + i] = p1; else sm[SMF_XK + i] = p0;
        __syncthreads();                                               // B5
        kv = tanh_fast((half ? p1 : p0) + sm[SMF_XK + half * 128 + i] + bn_i);
        ksum = fmaf(2.0f, kv, ksum);
        sm[SMF_S + half * 128 + i] = fmaf(dt, kv, hreg);
        __syncthreads();                                               // B6

        // ---------------- RK4 stage 4 + i-gate partials ----------------
        stage_partial(p0, p1);
        {
            float ir0 = 0.f, iz0 = 0.f, in0 = 0.f, ir1 = 0.f, iz1 = 0.f, in1 = 0.f;
#pragma unroll
            for (int p = 0; p < 8; p++) {
                float4 a = iu[p], b = iv[p];
                float4 wr = wihr[p], wz = wihz[p], wnn = wihn[p];
                DOT4_1(ir0, wr, a);  DOT4_1(ir1, wr, b);
                DOT4_1(iz0, wz, a);  DOT4_1(iz1, wz, b);
                DOT4_1(in0, wnn, a); DOT4_1(in1, wnn, b);
            }
            sm[SMF_IG + ((0 * 2 + 0) * 2 + half) * 128 + i] = ir0;
            sm[SMF_IG + ((0 * 2 + 1) * 2 + half) * 128 + i] = ir1;
            sm[SMF_IG + ((1 * 2 + 0) * 2 + half) * 128 + i] = iz0;
            sm[SMF_IG + ((1 * 2 + 1) * 2 + half) * 128 + i] = iz1;
            sm[SMF_IG + ((2 * 2 + 0) * 2 + half) * 128 + i] = in0;
            sm[SMF_IG + ((2 * 2 + 1) * 2 + half) * 128 + i] = in1;
        }
        if (half == 0) sm[SMF_XK + 128 + i] = p1; else sm[SMF_XK + i] = p0;
        __syncthreads();                                               // B7
        kv = tanh_fast((half ? p1 : p0) + sm[SMF_XK + half * 128 + i] + bn_i);
        const float hode = fmaf(dt * (1.0f / 6.0f), ksum + kv, hreg);
        sm[SMF_HO + half * 128 + i] = hode;
        __syncthreads();                                               // B8

        // ---------------- GRU: W_hh partial (both rows, my k-half) ----------------
        float r0 = 0.f, z0 = 0.f, n0 = 0.f, r1 = 0.f, z1 = 0.f, n1 = 0.f;
#pragma unroll
        for (int q = 0; q < 16; q++) {
            float4 a = hu[q], b = hv[q];
            float4 wr = WR[q * 128 + i];
            float4 wz = WZ[q * 128 + i];
            float4 wnn = WN[q * 128 + i];
            DOT4_1(r0, wr, a);  DOT4_1(r1, wr, b);
            DOT4_1(z0, wz, a);  DOT4_1(z1, wz, b);
            DOT4_1(n0, wnn, a); DOT4_1(n1, wnn, b);
        }
        {
            int fr = half ^ 1;
            sm[SMF_WH + (0 * 2 + fr) * 128 + i] = half ? r0 : r1;
            sm[SMF_WH + (1 * 2 + fr) * 128 + i] = half ? z0 : z1;
            sm[SMF_WH + (2 * 2 + fr) * 128 + i] = half ? n0 : n1;
        }
        __syncthreads();                                               // B9

        // ---------------- gate combine + blend ----------------
        {
            float hrT = (half ? r1 : r0) + sm[SMF_WH + (0 * 2 + half) * 128 + i];
            float hzT = (half ? z1 : z0) + sm[SMF_WH + (1 * 2 + half) * 128 + i];
            float hnT = (half ? n1 : n0) + sm[SMF_WH + (2 * 2 + half) * 128 + i];
            float irT = sm[SMF_IG + ((0 * 2 + half) * 2 + 0) * 128 + i]
                      + sm[SMF_IG + ((0 * 2 + half) * 2 + 1) * 128 + i];
            float izT = sm[SMF_IG + ((1 * 2 + half) * 2 + 0) * 128 + i]
                      + sm[SMF_IG + ((1 * 2 + half) * 2 + 1) * 128 + i];
            float inT = sm[SMF_IG + ((2 * 2 + half) * 2 + 0) * 128 + i]
                      + sm[SMF_IG + ((2 * 2 + half) * 2 + 1) * 128 + i];

            float rr = sigmoidf_(irT + sm[SMF_BIH + i]       + hrT + sm[SMF_BHH + i]);
            float zz = sigmoidf_(izT + sm[SMF_BIH + 128 + i] + hzT + sm[SMF_BHH + 128 + i]);
            float nn = tanhf(inT + sm[SMF_BIH + 256 + i] + rr * (hnT + sm[SMF_BHH + 256 + i]));
            hreg = nn + zz * (hode - nn);
            sm[SMF_S + half * 128 + i] = hreg;
        }
        __syncthreads();                                               // B10

        // ---------------- output projection (also next prev_out) ----------------
        {
            const int kh = i >> 6, j = i & 63;
            const float4* hs = (const float4*)(sm + SMF_S + half * 128 + kh * 64);
            const float4* wo = g_wout4 + 16 * kh * 64;
            float a = 0.f, b = 0.f;
#pragma unroll
            for (int q = 0; q < 16; q++) {
                float4 w = wo[q * 64 + j];
                float4 u = hs[q];
                a = fmaf(w.x, u.x, a); b = fmaf(w.y, u.y, b);
                a = fmaf(w.z, u.z, a); b = fmaf(w.w, u.w, b);
            }
            float acc = a + b;
            if (kh) sm[SMF_XO + half * 64 + j] = acc;
            __syncthreads();                                           // B11
            if (!kh) {
                float y = acc + sm[SMF_XO + half * 64 + j] + sm[SMF_BOUT + j];
                orow[(size_t)t * DIN + j] = y;
                sm[SMF_PO + half * 64 + j] = y;
            }
            __syncthreads();                                           // B12
        }
    }
}

// ---------------------------------------------------------------------------
extern "C" void kernel_launch(void* const* d_in, const int* in_sizes, int n_in,
                              void* d_out, int out_size)
{
    const float*         x      = (const float*)d_in[0];
    const float*         tp     = (const float*)d_in[1];
    const unsigned char* mask   = (const unsigned char*)d_in[2];
    const float*         W_ih   = (const float*)d_in[3];
    const float*         W_hh   = (const float*)d_in[4];
    const float*         b_ih   = (const float*)d_in[5];
    const float*         b_hh   = (const float*)d_in[6];
    const float*         W_node = (const float*)d_in[7];
    const float*         b_node = (const float*)d_in[8];
    const float*         W_out  = (const float*)d_in[9];
    const float*         b_out  = (const float*)d_in[10];
    float*               out    = (float*)d_out;

    prep_kernel<<<32, 256>>>(W_hh, W_out, mask, tp);

    cudaFuncSetAttribute(enc_gruode_kernel,
                         cudaFuncAttributeMaxDynamicSharedMemorySize,
                         SMEM_BYTES);
    enc_gruode_kernel<<<B_ / 2, 256, SMEM_BYTES>>>(
        x, W_ih, b_ih, b_hh, W_node, b_node, b_out, out);
}